// round 7
// baseline (speedup 1.0000x reference)
#include <cuda_runtime.h>
#include <math.h>

#define NB 8

__constant__ float c_START_Y[NB] = {0.1f, 0.2f, 0.3f, 0.4f, 0.5f, 0.6f, 0.7f, 0.8f};
__constant__ float c_START_X[NB] = {0.8f, 0.7f, 0.6f, 0.5f, 0.4f, 0.3f, 0.2f, 0.1f};
__constant__ int   c_SIDE[NB]    = {1, 0, 1, 0, 1, 0, 1, 0};

#define MAX_B 4096
__device__ float g_params[NB * MAX_B * 5];

__device__ __forceinline__ float sigmoidf_(float v) {
    return 1.0f / (1.0f + __expf(-v));
}

// ---------------- f32x2 packed helpers (Blackwell FFMA2) --------------------
typedef unsigned long long ull;
__device__ __forceinline__ ull pk2(float x, float y) {
    ull r; asm("mov.b64 %0, {%1,%2};" : "=l"(r) : "f"(x), "f"(y)); return r;
}
__device__ __forceinline__ void upk2(float& x, float& y, ull v) {
    asm("mov.b64 {%0,%1}, %2;" : "=f"(x), "=f"(y) : "l"(v));
}
__device__ __forceinline__ ull fma2(ull a, ull b, ull c) {
    ull d; asm("fma.rn.f32x2 %0, %1, %2, %3;" : "=l"(d) : "l"(a), "l"(b), "l"(c)); return d;
}
__device__ __forceinline__ ull add2(ull a, ull b) {
    ull d; asm("add.rn.f32x2 %0, %1, %2;" : "=l"(d) : "l"(a), "l"(b)); return d;
}
__device__ __forceinline__ ull mul2(ull a, ull b) {
    ull d; asm("mul.rn.f32x2 %0, %1, %2;" : "=l"(d) : "l"(a), "l"(b)); return d;
}

// ---------------------------------------------------------------------------
// Encode: per-blob MLP -> quadratic-form splat coefficients (unchanged, passes)
// ---------------------------------------------------------------------------
__global__ void encode_kernel(const float* __restrict__ positions,
                              const float* __restrict__ W1, const float* __restrict__ b1,
                              const float* __restrict__ W2, const float* __restrict__ b2,
                              const float* __restrict__ W3, const float* __restrict__ b3,
                              const float* __restrict__ scale_ptr, int B)
{
    const int i  = blockIdx.y;
    const int ty = threadIdx.y;
    const int k  = threadIdx.x;
    const int b  = blockIdx.x * 4 + ty;
    const bool valid = (b < B);

    __shared__ float sh_h[4][64];
    __shared__ float sh_bd[4][5];

    float h = 0.0f;
    if (valid) {
        const float* p = positions + (size_t)b * 6 + (c_SIDE[i] ? 0 : 3);
        float p0 = p[0] * 100.0f, p1 = p[1] * 100.0f, p2 = p[2] * 100.0f;
        const float* w1 = W1 + (size_t)i * 3 * 64;
        h = fmaf(p0, w1[k], fmaf(p1, w1[64 + k], fmaf(p2, w1[128 + k], b1[i * 64 + k])));
        h = fmaxf(h, 0.0f);
    }
    sh_h[ty][k] = h;
    __syncthreads();

    float acc = b2[i * 64 + k];
    {
        const float* w2 = W2 + (size_t)i * 64 * 64 + k;
        #pragma unroll 8
        for (int hh = 0; hh < 64; hh++)
            acc = fmaf(sh_h[ty][hh], w2[hh * 64], acc);
        acc = fmaxf(acc, 0.0f);
    }
    __syncthreads();
    sh_h[ty][k] = acc;
    __syncthreads();

    if (k < 5) {
        float o = b3[i * 5 + k];
        const float* w3 = W3 + (size_t)i * 64 * 5 + k;
        #pragma unroll 8
        for (int hh = 0; hh < 64; hh++)
            o = fmaf(sh_h[ty][hh], w3[hh * 5], o);
        sh_bd[ty][k] = o;
    }
    __syncthreads();

    if (k == 0 && valid) {
        float bd0 = sh_bd[ty][0], bd1 = sh_bd[ty][1], bd2 = sh_bd[ty][2];
        float bd3 = sh_bd[ty][3], bd4 = sh_bd[ty][4];
        float scale = *scale_ptr;

        float y  = sigmoidf_(bd0) + c_START_Y[i];
        float x  = sigmoidf_(bd1) + c_START_X[i];
        float s  = (bd2 + 0.05f) * scale;
        float a  = 0.5f + sigmoidf_(bd3) * 1.5f;
        float th = sigmoidf_(bd4) * 3.14159265358979323846f;

        float sa = s * a + 1e-6f;
        float sb = s / (a + 1e-6f) + 1e-6f;
        float A  = 0.5f / (sa * sa);
        float Bq = 0.5f / (sb * sb);

        float sn, c;
        sincosf(th, &sn, &c);

        const float L = 1.4426950408889634f;
        float al = -L * (A * c * c + Bq * sn * sn);
        float be = -L * (A * sn * sn + Bq * c * c);
        float ga = -2.0f * L * (A - Bq) * c * sn;

        float* o = g_params + ((size_t)i * B + b) * 5;
        o[0] = y; o[1] = x; o[2] = al; o[3] = be; o[4] = ga;
    }
}

// ---------------------------------------------------------------------------
// Splat: warp = row; lane owns 4 consecutive pixels = two independent f32x2
// chains (ILP=2); float4 stores. Static pipe split: blobs in TRICK_MASK use
// FMA-only exp2 (magic range reduction + deg-4 poly), rest use MUFU ex2.
// ---------------------------------------------------------------------------

#define TRICK_MASK 0x11u   // blobs 0,4 on the FMA path; 6 blobs on MUFU

// deg-4 Taylor of 2^f on f in [-0.5, 0.5]  (rel err <= 4.5e-5)
#define E2C0 1.0000000000f
#define E2C1 0.6931471806f
#define E2C2 0.2402265070f
#define E2C3 0.0555041087f
#define E2C4 0.0096181291f

#define MAGIC 12582912.0f   // 1.5 * 2^23

// FMA-pipe exp2 for packed e (e <= 0), clamped at -126
__device__ __forceinline__ ull exp2_fma2(ull e, ull M2, ull NEGM2, ull NEG1,
                                         ull P4, ull P3, ull P2, ull P1, ull P0)
{
    float elo, ehi;
    upk2(elo, ehi, e);
    elo = fmaxf(elo, -126.0f);
    ehi = fmaxf(ehi, -126.0f);
    ull ec = pk2(elo, ehi);
    ull t  = add2(ec, M2);                 // MAGIC + round(e)
    ull kf = add2(t, NEGM2);               // k = round(e), exact (Sterbenz)
    ull f  = fma2(kf, NEG1, ec);           // f = e - k in [-0.5,0.5], exact
    float tlo, thi;
    upk2(tlo, thi, t);
    unsigned slo = (__float_as_uint(tlo) << 23) + 0x3F800000u;
    unsigned shi = (__float_as_uint(thi) << 23) + 0x3F800000u;
    ull sc = pk2(__uint_as_float(slo), __uint_as_float(shi));  // 2^k
    ull p = fma2(P4, f, P3);
    p = fma2(p, f, P2);
    p = fma2(p, f, P1);
    p = fma2(p, f, P0);
    return mul2(p, sc);                    // 2^k * 2^f
}

__device__ __forceinline__ ull exp2_mufu2(ull e)
{
    float ex, ey, cx, cy;
    upk2(ex, ey, e);
    asm("ex2.approx.ftz.f32 %0, %1;" : "=f"(cx) : "f"(ex));
    asm("ex2.approx.ftz.f32 %0, %1;" : "=f"(cy) : "f"(ey));
    return pk2(cx, cy);
}

template<int NC2>   // number of 128-px chunks per row
__global__ void __launch_bounds__(256) splat_fast(float* __restrict__ out,
                                                  int B, int T, float invT)
{
    const int b    = blockIdx.y;
    const int tid  = threadIdx.x;
    const int lane = tid & 31;
    const int r    = tid >> 5;
    const int row  = blockIdx.x * 8 + r;

    __shared__ float sp[NB * 5];
    if (tid < NB * 5) {
        int i = tid / 5, f = tid - i * 5;
        sp[tid] = g_params[((size_t)i * B + b) * 5 + f];
    }
    __syncthreads();
    if (row >= T) return;

    const float rowc = ((float)row + 0.5f) * invT;

    // per-blob row quadratic e(w) = K2 w^2 + K1 w + K0  (e <= 0), warp-uniform
    float K2[NB], K1[NB], K0[NB];
    #pragma unroll
    for (int i = 0; i < NB; i++) {
        float y  = sp[i * 5 + 0];
        float x  = sp[i * 5 + 1];
        float al = sp[i * 5 + 2];
        float be = sp[i * 5 + 3];
        float ga = sp[i * 5 + 4];
        float dy = rowc - y;
        K2[i] = be;
        K1[i] = fmaf(ga, dy, -2.0f * be * x);
        float m = fmaf(al, dy, -(ga * x));
        K0[i] = fmaf(m, dy, be * x * x);
    }

    const ull M2    = pk2(MAGIC, MAGIC);
    const ull NEGM2 = pk2(-MAGIC, -MAGIC);
    const ull NEG1  = pk2(-1.0f, -1.0f);
    const ull P4 = pk2(E2C4, E2C4), P3 = pk2(E2C3, E2C3), P2 = pk2(E2C2, E2C2);
    const ull P1 = pk2(E2C1, E2C1), P0 = pk2(E2C0, E2C0);

    float4* orow = reinterpret_cast<float4*>(out + ((size_t)b * T + row) * T);

    const float wbase = ((float)(4 * lane) + 0.5f) * invT;
    const float wstep = 128.0f * invT;

    #pragma unroll 1
    for (int c = 0; c < NC2; c++) {
        float w0 = fmaf((float)c, wstep, wbase);
        ull wA = pk2(w0, w0 + invT);
        ull wB = pk2(w0 + 2.0f * invT, w0 + 3.0f * invT);
        ull imgA = 0ull, imgB = 0ull;

        #pragma unroll
        for (int i = 0; i < NB; i++) {
            ull k2p = pk2(K2[i], K2[i]);
            ull k1p = pk2(K1[i], K1[i]);
            ull k0p = pk2(K0[i], K0[i]);
            ull eA = fma2(fma2(k2p, wA, k1p), wA, k0p);
            ull eB = fma2(fma2(k2p, wB, k1p), wB, k0p);
            ull curA, curB;
            if ((TRICK_MASK >> i) & 1) {
                curA = exp2_fma2(eA, M2, NEGM2, NEG1, P4, P3, P2, P1, P0);
                curB = exp2_fma2(eB, M2, NEGM2, NEG1, P4, P3, P2, P1, P0);
            } else {
                curA = exp2_mufu2(eA);
                curB = exp2_mufu2(eB);
            }
            imgA = fma2(imgA, curA, curA);      // reference blend order
            imgB = fma2(imgB, curB, curB);
        }

        float ax, ay, bx, by;
        upk2(ax, ay, imgA);
        upk2(bx, by, imgB);
        orow[c * 32 + lane] = make_float4(ax, ay, bx, by);
    }
}

// ---------------------------------------------------------------------------
// Generic fallback splat (round-2 kernel, known correct for any T).
// ---------------------------------------------------------------------------
__global__ void __launch_bounds__(256) splat_kernel(float* __restrict__ out,
                                                    int B, int T, float invT)
{
    const int b    = blockIdx.y;
    const int tid  = threadIdx.x;
    const int lane = tid & 31;
    const int r    = tid >> 5;
    const int row  = blockIdx.x * 8 + r;

    __shared__ float sp[NB * 5];
    if (tid < NB * 5) {
        int i = tid / 5, f = tid - i * 5;
        sp[tid] = g_params[((size_t)i * B + b) * 5 + f];
    }
    __syncthreads();
    if (row >= T) return;

    const float rowc = ((float)row + 0.5f) * invT;

    float K2[NB], K1[NB], K0[NB];
    #pragma unroll
    for (int i = 0; i < NB; i++) {
        float y  = sp[i * 5 + 0];
        float x  = sp[i * 5 + 1];
        float al = sp[i * 5 + 2];
        float be = sp[i * 5 + 3];
        float ga = sp[i * 5 + 4];
        float dy = rowc - y;
        K2[i] = be;
        K1[i] = fmaf(ga, dy, -2.0f * be * x);
        float m = fmaf(al, dy, -(ga * x));
        K0[i] = fmaf(m, dy, be * x * x);
    }

    float* orow = out + ((size_t)b * T + row) * T;
    const int nj = (T + 31) >> 5;

    for (int j = 0; j < nj; j++) {
        int col = lane + (j << 5);
        if (col >= T) break;
        float w = ((float)col + 0.5f) * invT;
        float img = 0.0f;
        #pragma unroll
        for (int i = 0; i < NB; i++) {
            float e = fmaf(fmaf(K2[i], w, K1[i]), w, K0[i]);
            float cur;
            asm("ex2.approx.ftz.f32 %0, %1;" : "=f"(cur) : "f"(e));
            img = fmaf(img, cur, cur);
        }
        orow[col] = img;
    }
}

// ---------------------------------------------------------------------------
extern "C" void kernel_launch(void* const* d_in, const int* in_sizes, int n_in,
                              void* d_out, int out_size)
{
    const float* positions = (const float*)d_in[0];
    const float* W1 = (const float*)d_in[1];
    const float* b1 = (const float*)d_in[2];
    const float* W2 = (const float*)d_in[3];
    const float* b2 = (const float*)d_in[4];
    const float* W3 = (const float*)d_in[5];
    const float* b3 = (const float*)d_in[6];
    const float* scale = (const float*)d_in[n_in - 1];

    int B = in_sizes[0] / 6;
    if (B > MAX_B) B = MAX_B;
    int T = (int)(sqrt((double)out_size / (double)B) + 0.5);
    float invT = 1.0f / (float)T;

    dim3 egrid((B + 3) / 4, NB);
    dim3 eblock(64, 4);
    encode_kernel<<<egrid, eblock>>>(positions, W1, b1, W2, b2, W3, b3, scale, B);

    dim3 sgrid((T + 7) / 8, B);
    if (T == 256)
        splat_fast<2><<<sgrid, 256>>>((float*)d_out, B, T, invT);
    else if (T == 128)
        splat_fast<1><<<sgrid, 256>>>((float*)d_out, B, T, invT);
    else
        splat_kernel<<<sgrid, 256>>>((float*)d_out, B, T, invT);
}

// round 8
// speedup vs baseline: 1.0028x; 1.0028x over previous
#include <cuda_runtime.h>
#include <math.h>

#define NB 8

__constant__ float c_START_Y[NB] = {0.1f, 0.2f, 0.3f, 0.4f, 0.5f, 0.6f, 0.7f, 0.8f};
__constant__ float c_START_X[NB] = {0.8f, 0.7f, 0.6f, 0.5f, 0.4f, 0.3f, 0.2f, 0.1f};
__constant__ int   c_SIDE[NB]    = {1, 0, 1, 0, 1, 0, 1, 0};

#define MAX_B 4096
__device__ float g_params[NB * MAX_B * 5];

__device__ __forceinline__ float sigmoidf_(float v) {
    return 1.0f / (1.0f + __expf(-v));
}

// ---------------- f32x2 packed helpers (Blackwell FFMA2) --------------------
typedef unsigned long long ull;
__device__ __forceinline__ ull pk2(float x, float y) {
    ull r; asm("mov.b64 %0, {%1,%2};" : "=l"(r) : "f"(x), "f"(y)); return r;
}
__device__ __forceinline__ void upk2(float& x, float& y, ull v) {
    asm("mov.b64 {%0,%1}, %2;" : "=f"(x), "=f"(y) : "l"(v));
}
__device__ __forceinline__ ull fma2(ull a, ull b, ull c) {
    ull d; asm("fma.rn.f32x2 %0, %1, %2, %3;" : "=l"(d) : "l"(a), "l"(b), "l"(c)); return d;
}
__device__ __forceinline__ ull add2(ull a, ull b) {
    ull d; asm("add.rn.f32x2 %0, %1, %2;" : "=l"(d) : "l"(a), "l"(b)); return d;
}
__device__ __forceinline__ ull sub2(ull a, ull b) {
    ull d; asm("sub.rn.f32x2 %0, %1, %2;" : "=l"(d) : "l"(a), "l"(b)); return d;
}
__device__ __forceinline__ ull mul2(ull a, ull b) {
    ull d; asm("mul.rn.f32x2 %0, %1, %2;" : "=l"(d) : "l"(a), "l"(b)); return d;
}

// ---------------------------------------------------------------------------
// Encode: per-blob MLP -> quadratic-form splat coefficients (unchanged, passes)
// ---------------------------------------------------------------------------
__global__ void encode_kernel(const float* __restrict__ positions,
                              const float* __restrict__ W1, const float* __restrict__ b1,
                              const float* __restrict__ W2, const float* __restrict__ b2,
                              const float* __restrict__ W3, const float* __restrict__ b3,
                              const float* __restrict__ scale_ptr, int B)
{
    const int i  = blockIdx.y;
    const int ty = threadIdx.y;
    const int k  = threadIdx.x;
    const int b  = blockIdx.x * 4 + ty;
    const bool valid = (b < B);

    __shared__ float sh_h[4][64];
    __shared__ float sh_bd[4][5];

    float h = 0.0f;
    if (valid) {
        const float* p = positions + (size_t)b * 6 + (c_SIDE[i] ? 0 : 3);
        float p0 = p[0] * 100.0f, p1 = p[1] * 100.0f, p2 = p[2] * 100.0f;
        const float* w1 = W1 + (size_t)i * 3 * 64;
        h = fmaf(p0, w1[k], fmaf(p1, w1[64 + k], fmaf(p2, w1[128 + k], b1[i * 64 + k])));
        h = fmaxf(h, 0.0f);
    }
    sh_h[ty][k] = h;
    __syncthreads();

    float acc = b2[i * 64 + k];
    {
        const float* w2 = W2 + (size_t)i * 64 * 64 + k;
        #pragma unroll 8
        for (int hh = 0; hh < 64; hh++)
            acc = fmaf(sh_h[ty][hh], w2[hh * 64], acc);
        acc = fmaxf(acc, 0.0f);
    }
    __syncthreads();
    sh_h[ty][k] = acc;
    __syncthreads();

    if (k < 5) {
        float o = b3[i * 5 + k];
        const float* w3 = W3 + (size_t)i * 64 * 5 + k;
        #pragma unroll 8
        for (int hh = 0; hh < 64; hh++)
            o = fmaf(sh_h[ty][hh], w3[hh * 5], o);
        sh_bd[ty][k] = o;
    }
    __syncthreads();

    if (k == 0 && valid) {
        float bd0 = sh_bd[ty][0], bd1 = sh_bd[ty][1], bd2 = sh_bd[ty][2];
        float bd3 = sh_bd[ty][3], bd4 = sh_bd[ty][4];
        float scale = *scale_ptr;

        float y  = sigmoidf_(bd0) + c_START_Y[i];
        float x  = sigmoidf_(bd1) + c_START_X[i];
        float s  = (bd2 + 0.05f) * scale;
        float a  = 0.5f + sigmoidf_(bd3) * 1.5f;
        float th = sigmoidf_(bd4) * 3.14159265358979323846f;

        float sa = s * a + 1e-6f;
        float sb = s / (a + 1e-6f) + 1e-6f;
        float A  = 0.5f / (sa * sa);
        float Bq = 0.5f / (sb * sb);

        float sn, c;
        sincosf(th, &sn, &c);

        const float L = 1.4426950408889634f;
        float al = -L * (A * c * c + Bq * sn * sn);
        float be = -L * (A * sn * sn + Bq * c * c);
        float ga = -2.0f * L * (A - Bq) * c * sn;

        float* o = g_params + ((size_t)i * B + b) * 5;
        o[0] = y; o[1] = x; o[2] = al; o[3] = be; o[4] = ga;
    }
}

// ---------------------------------------------------------------------------
// Splat: warp = row; lane owns 4 consecutive pixels = two independent f32x2
// chains; float4 stores. Static pipe split: blobs in TRICK_MASK use FMA-only
// exp2 (magic range reduction + deg-3 economized poly), rest use MUFU ex2.
// Register-trimmed (deg-3 poly, sub2 instead of extra constants) and
// __launch_bounds__(256,6) to lift occupancy to 48 warps/SM.
// ---------------------------------------------------------------------------

#define TRICK_MASK 0x11u   // blobs 0,4 on the FMA path; 6 blobs on MUFU

// deg-3 economized poly for 2^f on f in [-0.5,0.5]  (rel err ~1.2e-4)
#define E3C0 0.9999248720f
#define E3C1 0.6931471806f
#define E3C2 0.2426310393f
#define E3C3 0.0555041087f

#define MAGIC 12582912.0f   // 1.5 * 2^23

// FMA-pipe exp2 for packed e (e <= 0), clamped at -126
__device__ __forceinline__ ull exp2_fma2(ull e, ull M2, ull P3, ull P2, ull P1, ull P0)
{
    float elo, ehi;
    upk2(elo, ehi, e);
    elo = fmaxf(elo, -126.0f);
    ehi = fmaxf(ehi, -126.0f);
    ull ec = pk2(elo, ehi);
    ull t  = add2(ec, M2);                 // MAGIC + round(e)
    ull kf = sub2(t, M2);                  // k = round(e), exact (Sterbenz)
    ull f  = sub2(ec, kf);                 // f = e - k in [-0.5,0.5], exact
    float tlo, thi;
    upk2(tlo, thi, t);
    unsigned slo = (__float_as_uint(tlo) << 23) + 0x3F800000u;
    unsigned shi = (__float_as_uint(thi) << 23) + 0x3F800000u;
    ull sc = pk2(__uint_as_float(slo), __uint_as_float(shi));  // 2^k
    ull p = fma2(P3, f, P2);
    p = fma2(p, f, P1);
    p = fma2(p, f, P0);
    return mul2(p, sc);                    // 2^k * 2^f
}

__device__ __forceinline__ ull exp2_mufu2(ull e)
{
    float ex, ey, cx, cy;
    upk2(ex, ey, e);
    asm("ex2.approx.ftz.f32 %0, %1;" : "=f"(cx) : "f"(ex));
    asm("ex2.approx.ftz.f32 %0, %1;" : "=f"(cy) : "f"(ey));
    return pk2(cx, cy);
}

template<int NC2>   // number of 128-px chunks per row
__global__ void __launch_bounds__(256, 6) splat_fast(float* __restrict__ out,
                                                     int B, int T, float invT)
{
    const int b    = blockIdx.y;
    const int tid  = threadIdx.x;
    const int lane = tid & 31;
    const int r    = tid >> 5;
    const int row  = blockIdx.x * 8 + r;

    __shared__ float sp[NB * 5];
    if (tid < NB * 5) {
        int i = tid / 5, f = tid - i * 5;
        sp[tid] = g_params[((size_t)i * B + b) * 5 + f];
    }
    __syncthreads();
    if (row >= T) return;

    const float rowc = ((float)row + 0.5f) * invT;

    // per-blob row quadratic e(w) = K2 w^2 + K1 w + K0  (e <= 0), warp-uniform
    float K2[NB], K1[NB], K0[NB];
    #pragma unroll
    for (int i = 0; i < NB; i++) {
        float y  = sp[i * 5 + 0];
        float x  = sp[i * 5 + 1];
        float al = sp[i * 5 + 2];
        float be = sp[i * 5 + 3];
        float ga = sp[i * 5 + 4];
        float dy = rowc - y;
        K2[i] = be;
        K1[i] = fmaf(ga, dy, -2.0f * be * x);
        float m = fmaf(al, dy, -(ga * x));
        K0[i] = fmaf(m, dy, be * x * x);
    }

    const ull M2 = pk2(MAGIC, MAGIC);
    const ull P3 = pk2(E3C3, E3C3), P2 = pk2(E3C2, E3C2);
    const ull P1 = pk2(E3C1, E3C1), P0 = pk2(E3C0, E3C0);

    float4* orow = reinterpret_cast<float4*>(out + ((size_t)b * T + row) * T);

    const float wbase = ((float)(4 * lane) + 0.5f) * invT;
    const float wstep = 128.0f * invT;

    #pragma unroll 1
    for (int c = 0; c < NC2; c++) {
        float w0 = fmaf((float)c, wstep, wbase);
        ull wA = pk2(w0, w0 + invT);
        ull wB = pk2(w0 + 2.0f * invT, w0 + 3.0f * invT);
        ull imgA = 0ull, imgB = 0ull;

        #pragma unroll
        for (int i = 0; i < NB; i++) {
            ull k2p = pk2(K2[i], K2[i]);
            ull k1p = pk2(K1[i], K1[i]);
            ull k0p = pk2(K0[i], K0[i]);
            ull eA = fma2(fma2(k2p, wA, k1p), wA, k0p);
            ull eB = fma2(fma2(k2p, wB, k1p), wB, k0p);
            ull curA, curB;
            if ((TRICK_MASK >> i) & 1) {
                curA = exp2_fma2(eA, M2, P3, P2, P1, P0);
                curB = exp2_fma2(eB, M2, P3, P2, P1, P0);
            } else {
                curA = exp2_mufu2(eA);
                curB = exp2_mufu2(eB);
            }
            imgA = fma2(imgA, curA, curA);      // reference blend order
            imgB = fma2(imgB, curB, curB);
        }

        float ax, ay, bx, by;
        upk2(ax, ay, imgA);
        upk2(bx, by, imgB);
        orow[c * 32 + lane] = make_float4(ax, ay, bx, by);
    }
}

// ---------------------------------------------------------------------------
// Generic fallback splat (round-2 kernel, known correct for any T).
// ---------------------------------------------------------------------------
__global__ void __launch_bounds__(256) splat_kernel(float* __restrict__ out,
                                                    int B, int T, float invT)
{
    const int b    = blockIdx.y;
    const int tid  = threadIdx.x;
    const int lane = tid & 31;
    const int r    = tid >> 5;
    const int row  = blockIdx.x * 8 + r;

    __shared__ float sp[NB * 5];
    if (tid < NB * 5) {
        int i = tid / 5, f = tid - i * 5;
        sp[tid] = g_params[((size_t)i * B + b) * 5 + f];
    }
    __syncthreads();
    if (row >= T) return;

    const float rowc = ((float)row + 0.5f) * invT;

    float K2[NB], K1[NB], K0[NB];
    #pragma unroll
    for (int i = 0; i < NB; i++) {
        float y  = sp[i * 5 + 0];
        float x  = sp[i * 5 + 1];
        float al = sp[i * 5 + 2];
        float be = sp[i * 5 + 3];
        float ga = sp[i * 5 + 4];
        float dy = rowc - y;
        K2[i] = be;
        K1[i] = fmaf(ga, dy, -2.0f * be * x);
        float m = fmaf(al, dy, -(ga * x));
        K0[i] = fmaf(m, dy, be * x * x);
    }

    float* orow = out + ((size_t)b * T + row) * T;
    const int nj = (T + 31) >> 5;

    for (int j = 0; j < nj; j++) {
        int col = lane + (j << 5);
        if (col >= T) break;
        float w = ((float)col + 0.5f) * invT;
        float img = 0.0f;
        #pragma unroll
        for (int i = 0; i < NB; i++) {
            float e = fmaf(fmaf(K2[i], w, K1[i]), w, K0[i]);
            float cur;
            asm("ex2.approx.ftz.f32 %0, %1;" : "=f"(cur) : "f"(e));
            img = fmaf(img, cur, cur);
        }
        orow[col] = img;
    }
}

// ---------------------------------------------------------------------------
extern "C" void kernel_launch(void* const* d_in, const int* in_sizes, int n_in,
                              void* d_out, int out_size)
{
    const float* positions = (const float*)d_in[0];
    const float* W1 = (const float*)d_in[1];
    const float* b1 = (const float*)d_in[2];
    const float* W2 = (const float*)d_in[3];
    const float* b2 = (const float*)d_in[4];
    const float* W3 = (const float*)d_in[5];
    const float* b3 = (const float*)d_in[6];
    const float* scale = (const float*)d_in[n_in - 1];

    int B = in_sizes[0] / 6;
    if (B > MAX_B) B = MAX_B;
    int T = (int)(sqrt((double)out_size / (double)B) + 0.5);
    float invT = 1.0f / (float)T;

    dim3 egrid((B + 3) / 4, NB);
    dim3 eblock(64, 4);
    encode_kernel<<<egrid, eblock>>>(positions, W1, b1, W2, b2, W3, b3, scale, B);

    dim3 sgrid((T + 7) / 8, B);
    if (T == 256)
        splat_fast<2><<<sgrid, 256>>>((float*)d_out, B, T, invT);
    else if (T == 128)
        splat_fast<1><<<sgrid, 256>>>((float*)d_out, B, T, invT);
    else
        splat_kernel<<<sgrid, 256>>>((float*)d_out, B, T, invT);
}

// round 9
// speedup vs baseline: 1.1794x; 1.1761x over previous
#include <cuda_runtime.h>
#include <math.h>

#define NB 8

__constant__ float c_START_Y[NB] = {0.1f, 0.2f, 0.3f, 0.4f, 0.5f, 0.6f, 0.7f, 0.8f};
__constant__ float c_START_X[NB] = {0.8f, 0.7f, 0.6f, 0.5f, 0.4f, 0.3f, 0.2f, 0.1f};
__constant__ int   c_SIDE[NB]    = {1, 0, 1, 0, 1, 0, 1, 0};

#define MAX_B 4096
__device__ float g_params[NB * MAX_B * 5];

__device__ __forceinline__ float sigmoidf_(float v) {
    return 1.0f / (1.0f + __expf(-v));
}

// ---------------- f32x2 packed helpers (Blackwell FFMA2) --------------------
typedef unsigned long long ull;
__device__ __forceinline__ ull pk2(float x, float y) {
    ull r; asm("mov.b64 %0, {%1,%2};" : "=l"(r) : "f"(x), "f"(y)); return r;
}
__device__ __forceinline__ void upk2(float& x, float& y, ull v) {
    asm("mov.b64 {%0,%1}, %2;" : "=f"(x), "=f"(y) : "l"(v));
}
__device__ __forceinline__ ull fma2(ull a, ull b, ull c) {
    ull d; asm("fma.rn.f32x2 %0, %1, %2, %3;" : "=l"(d) : "l"(a), "l"(b), "l"(c)); return d;
}

// ---------------------------------------------------------------------------
// Encode: per-blob MLP -> quadratic-form splat coefficients (unchanged, passes)
// ---------------------------------------------------------------------------
__global__ void encode_kernel(const float* __restrict__ positions,
                              const float* __restrict__ W1, const float* __restrict__ b1,
                              const float* __restrict__ W2, const float* __restrict__ b2,
                              const float* __restrict__ W3, const float* __restrict__ b3,
                              const float* __restrict__ scale_ptr, int B)
{
    const int i  = blockIdx.y;
    const int ty = threadIdx.y;
    const int k  = threadIdx.x;
    const int b  = blockIdx.x * 4 + ty;
    const bool valid = (b < B);

    __shared__ float sh_h[4][64];
    __shared__ float sh_bd[4][5];

    float h = 0.0f;
    if (valid) {
        const float* p = positions + (size_t)b * 6 + (c_SIDE[i] ? 0 : 3);
        float p0 = p[0] * 100.0f, p1 = p[1] * 100.0f, p2 = p[2] * 100.0f;
        const float* w1 = W1 + (size_t)i * 3 * 64;
        h = fmaf(p0, w1[k], fmaf(p1, w1[64 + k], fmaf(p2, w1[128 + k], b1[i * 64 + k])));
        h = fmaxf(h, 0.0f);
    }
    sh_h[ty][k] = h;
    __syncthreads();

    float acc = b2[i * 64 + k];
    {
        const float* w2 = W2 + (size_t)i * 64 * 64 + k;
        #pragma unroll 8
        for (int hh = 0; hh < 64; hh++)
            acc = fmaf(sh_h[ty][hh], w2[hh * 64], acc);
        acc = fmaxf(acc, 0.0f);
    }
    __syncthreads();
    sh_h[ty][k] = acc;
    __syncthreads();

    if (k < 5) {
        float o = b3[i * 5 + k];
        const float* w3 = W3 + (size_t)i * 64 * 5 + k;
        #pragma unroll 8
        for (int hh = 0; hh < 64; hh++)
            o = fmaf(sh_h[ty][hh], w3[hh * 5], o);
        sh_bd[ty][k] = o;
    }
    __syncthreads();

    if (k == 0 && valid) {
        float bd0 = sh_bd[ty][0], bd1 = sh_bd[ty][1], bd2 = sh_bd[ty][2];
        float bd3 = sh_bd[ty][3], bd4 = sh_bd[ty][4];
        float scale = *scale_ptr;

        float y  = sigmoidf_(bd0) + c_START_Y[i];
        float x  = sigmoidf_(bd1) + c_START_X[i];
        float s  = (bd2 + 0.05f) * scale;
        float a  = 0.5f + sigmoidf_(bd3) * 1.5f;
        float th = sigmoidf_(bd4) * 3.14159265358979323846f;

        float sa = s * a + 1e-6f;
        float sb = s / (a + 1e-6f) + 1e-6f;
        float A  = 0.5f / (sa * sa);
        float Bq = 0.5f / (sb * sb);

        float sn, c;
        sincosf(th, &sn, &c);

        const float L = 1.4426950408889634f;
        float al = -L * (A * c * c + Bq * sn * sn);
        float be = -L * (A * sn * sn + Bq * c * c);
        float ga = -2.0f * L * (A - Bq) * c * sn;

        float* o = g_params + ((size_t)i * B + b) * 5;
        o[0] = y; o[1] = x; o[2] = al; o[3] = be; o[4] = ga;
    }
}

// ---------------------------------------------------------------------------
// Splat, issue-minimized: warp = row, lane = one f32x2 pixel pair, NC chunks
// of 64 px. Pure MUFU exp2. Packed coefficients hoisted out of the chunk loop
// (48 persistent regs). Per 64-px chunk: 8*(2 fma2 + 2 EX2 + 1 fma2 blend)
// + store + loop ~= 44 warp-issues (~0.69 issues/px vs ~1.09 before).
// ---------------------------------------------------------------------------
template<int NC>
__global__ void __launch_bounds__(256, 4) splat_fast(float* __restrict__ out,
                                                     int B, int T, float invT)
{
    const int b    = blockIdx.y;
    const int tid  = threadIdx.x;
    const int lane = tid & 31;
    const int r    = tid >> 5;
    const int row  = blockIdx.x * 8 + r;

    __shared__ float sp[NB * 5];
    if (tid < NB * 5) {
        int i = tid / 5, f = tid - i * 5;
        sp[tid] = g_params[((size_t)i * B + b) * 5 + f];
    }
    __syncthreads();
    if (row >= T) return;

    const float rowc = ((float)row + 0.5f) * invT;

    // per-blob row quadratic e(w) = K2 w^2 + K1 w + K0  (e <= 0), warp-uniform,
    // packed once per row (hoisted out of the pixel loop).
    ull k2p[NB], k1p[NB], k0p[NB];
    #pragma unroll
    for (int i = 0; i < NB; i++) {
        float y  = sp[i * 5 + 0];
        float x  = sp[i * 5 + 1];
        float al = sp[i * 5 + 2];
        float be = sp[i * 5 + 3];
        float ga = sp[i * 5 + 4];
        float dy = rowc - y;
        float K2 = be;
        float K1 = fmaf(ga, dy, -2.0f * be * x);
        float m  = fmaf(al, dy, -(ga * x));
        float K0 = fmaf(m, dy, be * x * x);
        k2p[i] = pk2(K2, K2);
        k1p[i] = pk2(K1, K1);
        k0p[i] = pk2(K0, K0);
    }

    float2* orow = reinterpret_cast<float2*>(out + ((size_t)b * T + row) * T);

    const float wbase = ((float)(2 * lane) + 0.5f) * invT;
    const float wstep = 64.0f * invT;

    #pragma unroll 1
    for (int c = 0; c < NC; c++) {
        float w0 = fmaf((float)c, wstep, wbase);
        ull w   = pk2(w0, w0 + invT);
        ull img = 0ull;

        #pragma unroll
        for (int i = 0; i < NB; i++) {
            ull e = fma2(fma2(k2p[i], w, k1p[i]), w, k0p[i]);
            float ex, ey, cx, cy;
            upk2(ex, ey, e);
            asm("ex2.approx.ftz.f32 %0, %1;" : "=f"(cx) : "f"(ex));
            asm("ex2.approx.ftz.f32 %0, %1;" : "=f"(cy) : "f"(ey));
            ull cur = pk2(cx, cy);
            img = fma2(img, cur, cur);          // reference blend order
        }

        float ix, iy;
        upk2(ix, iy, img);
        orow[c * 32 + lane] = make_float2(ix, iy);
    }
}

// ---------------------------------------------------------------------------
// Generic fallback splat (round-2 kernel, known correct for any T).
// ---------------------------------------------------------------------------
__global__ void __launch_bounds__(256) splat_kernel(float* __restrict__ out,
                                                    int B, int T, float invT)
{
    const int b    = blockIdx.y;
    const int tid  = threadIdx.x;
    const int lane = tid & 31;
    const int r    = tid >> 5;
    const int row  = blockIdx.x * 8 + r;

    __shared__ float sp[NB * 5];
    if (tid < NB * 5) {
        int i = tid / 5, f = tid - i * 5;
        sp[tid] = g_params[((size_t)i * B + b) * 5 + f];
    }
    __syncthreads();
    if (row >= T) return;

    const float rowc = ((float)row + 0.5f) * invT;

    float K2[NB], K1[NB], K0[NB];
    #pragma unroll
    for (int i = 0; i < NB; i++) {
        float y  = sp[i * 5 + 0];
        float x  = sp[i * 5 + 1];
        float al = sp[i * 5 + 2];
        float be = sp[i * 5 + 3];
        float ga = sp[i * 5 + 4];
        float dy = rowc - y;
        K2[i] = be;
        K1[i] = fmaf(ga, dy, -2.0f * be * x);
        float m = fmaf(al, dy, -(ga * x));
        K0[i] = fmaf(m, dy, be * x * x);
    }

    float* orow = out + ((size_t)b * T + row) * T;
    const int nj = (T + 31) >> 5;

    for (int j = 0; j < nj; j++) {
        int col = lane + (j << 5);
        if (col >= T) break;
        float w = ((float)col + 0.5f) * invT;
        float img = 0.0f;
        #pragma unroll
        for (int i = 0; i < NB; i++) {
            float e = fmaf(fmaf(K2[i], w, K1[i]), w, K0[i]);
            float cur;
            asm("ex2.approx.ftz.f32 %0, %1;" : "=f"(cur) : "f"(e));
            img = fmaf(img, cur, cur);
        }
        orow[col] = img;
    }
}

// ---------------------------------------------------------------------------
extern "C" void kernel_launch(void* const* d_in, const int* in_sizes, int n_in,
                              void* d_out, int out_size)
{
    const float* positions = (const float*)d_in[0];
    const float* W1 = (const float*)d_in[1];
    const float* b1 = (const float*)d_in[2];
    const float* W2 = (const float*)d_in[3];
    const float* b2 = (const float*)d_in[4];
    const float* W3 = (const float*)d_in[5];
    const float* b3 = (const float*)d_in[6];
    const float* scale = (const float*)d_in[n_in - 1];

    int B = in_sizes[0] / 6;
    if (B > MAX_B) B = MAX_B;
    int T = (int)(sqrt((double)out_size / (double)B) + 0.5);
    float invT = 1.0f / (float)T;

    dim3 egrid((B + 3) / 4, NB);
    dim3 eblock(64, 4);
    encode_kernel<<<egrid, eblock>>>(positions, W1, b1, W2, b2, W3, b3, scale, B);

    dim3 sgrid((T + 7) / 8, B);
    if (T == 256)
        splat_fast<4><<<sgrid, 256>>>((float*)d_out, B, T, invT);
    else if (T == 128)
        splat_fast<2><<<sgrid, 256>>>((float*)d_out, B, T, invT);
    else
        splat_kernel<<<sgrid, 256>>>((float*)d_out, B, T, invT);
}